// round 12
// baseline (speedup 1.0000x reference)
#include <cuda_runtime.h>
#include <cstdint>

// CRF loss: mean_b( logZ_b - gold_b )
// Forward recurrence in LINEAR space, one warp per batch, lane = state.
//   e_t[n] = (expM @ e_{t-1})[n] * exp(emit_t[n]) * 2^{-k},  off += k
// e broadcast via bf16x2-PACKED shuffles: 1 pair-exchange + 15 broadcasts
// (vs 30 f32 shfls / vs smem with its ~60cyc store-commit roundtrip).
// Lane state stays full f32; only broadcast copies are bf16-rounded (RTN via
// +0x8000, unbiased). Renorm every 4 steps reads e[0]'s exponent straight
// from broadcast word 0 (bf16 keeps the exponent) -> zero extra cost.
// Structural zeros: p=30 (e[START]=0 for t>=1) and p=31 (col STOP = 0)
// drop out -> 15 packed pairs. Gold score in its own parallel kernel.

#define KSTATES   32
#define START_IDX 30
#define STOP_IDX  31
#define FULLMASK  0xffffffffu
#define LN2       0.6931471805599453f

__device__ float    g_fwd[4096];
__device__ float    g_gold[4096];
__device__ unsigned g_count;          // zero-init; reset by last block

// Pack (e[2q], e[2q+1]) as bf16x2 in every lane of the pair.
// ebits must be pre-rounded: __float_as_uint(e) + 0x8000.
__device__ __forceinline__ unsigned crf_pack_pair(unsigned ebits, int lane)
{
    unsigned partner = __shfl_xor_sync(FULLMASK, ebits, 1);
    unsigned even_b  = (lane & 1) ? partner : ebits;
    unsigned odd_b   = (lane & 1) ? ebits   : partner;
    // bytes {even.b2, even.b3, odd.b2, odd.b3} -> (lo16=even_bf16, hi16=odd_bf16)
    return __byte_perm(even_b, odd_b, 0x7632);
}

// s[lane] = sum_{p=0..29} M[p] * e[p] from 15 packed broadcasts.
__device__ __forceinline__ float crf_dot_bf16(const float* __restrict__ M,
                                              unsigned packed)
{
    unsigned pq[15];
#pragma unroll
    for (int q = 0; q < 15; q++)
        pq[q] = __shfl_sync(FULLMASK, packed, 2 * q);

    float a0 = 0.f, a1 = 0.f, a2 = 0.f, a3 = 0.f, a4 = 0.f, a5 = 0.f;
#pragma unroll
    for (int q = 0; q < 15; q += 3) {
        a0 = fmaf(M[2*q    ], __uint_as_float(pq[q]     << 16),         a0);
        a1 = fmaf(M[2*q + 1], __uint_as_float(pq[q]      & 0xFFFF0000u), a1);
        a2 = fmaf(M[2*q + 2], __uint_as_float(pq[q + 1] << 16),         a2);
        a3 = fmaf(M[2*q + 3], __uint_as_float(pq[q + 1]  & 0xFFFF0000u), a3);
        a4 = fmaf(M[2*q + 4], __uint_as_float(pq[q + 2] << 16),         a4);
        a5 = fmaf(M[2*q + 5], __uint_as_float(pq[q + 2]  & 0xFFFF0000u), a5);
    }
    return ((a0 + a1) + (a2 + a3)) + (a4 + a5);
}

// 2^-k from broadcast word q=0's low bf16 (= e[0]'s exponent), k -> off.
__device__ __forceinline__ float crf_renorm_from_packed(unsigned p0, int& off)
{
    int ie = (int)((p0 >> 7) & 0xFF);       // exponent bits of lo bf16
    ie = (ie == 0) ? 127 : ie;              // guard zero/denormal
    off += ie - 127;
    return __uint_as_float((unsigned)(254 - ie) << 23);
}

__global__ void __launch_bounds__(32)
crf_forward_kernel(const float* __restrict__ feats,
                   const float* __restrict__ trans,
                   const int*   __restrict__ lens,
                   float* __restrict__ out,
                   int B, int T)
{
    const int lane = threadIdx.x & 31;
    const int b    = blockIdx.x;

    // Per-lane row of exp(transitions). exp(-10000) -> exactly 0:
    // row START (lane 30) all-zero, column STOP (p=31) all-zero.
    float M[30];
#pragma unroll
    for (int p = 0; p < 30; p++)
        M[p] = __expf(trans[lane * KSTATES + p]);

    const int len = lens[b];
    const float* fb = feats + (size_t)b * T * KSTATES + lane;

    // ---- t = 0 peeled: e[n] = exp(trans[n][START] + emit0[n]) ----
    float e   = __expf(trans[lane * KSTATES + START_IDX] + fb[0]);
    int   off = 0;
    unsigned packed = crf_pack_pair(__float_as_uint(e) + 0x8000u, lane);

    // ---- steps t = 1 .. len-1; 8-unrolled, 8-deep prefetch ----
    const int steps = len - 1;
    float fbuf[8];
#pragma unroll
    for (int i = 0; i < 8; i++)
        fbuf[i] = (1 + i < len) ? fb[(size_t)(1 + i) * KSTATES] : 0.0f;

    const int s8 = steps & ~7;
    for (int s0 = 0; s0 < s8; s0 += 8) {
#pragma unroll
        for (int j = 0; j < 8; j++) {
            float h = __expf(fbuf[j]);                   // MUFU, off-path
            if ((j & 3) == 0)                            // renorm every 4 steps
                h *= crf_renorm_from_packed(__shfl_sync(FULLMASK, packed, 0), off);
            float s = crf_dot_bf16(M, packed);
            e = s * h;
            packed = crf_pack_pair(__float_as_uint(e) + 0x8000u, lane);
            int tt = 9 + s0 + j;                         // reload slot j for step j+8
            fbuf[j] = (tt < len) ? fb[(size_t)tt * KSTATES] : 0.0f;
        }
    }
    for (int s = s8; s < steps; s++) {                   // <=7 step tail
        float h = __expf(fbuf[s - s8])
                * crf_renorm_from_packed(__shfl_sync(FULLMASK, packed, 0), off);
        float sv = crf_dot_bf16(M, packed);
        e = sv * h;
        packed = crf_pack_pair(__float_as_uint(e) + 0x8000u, lane);
    }

    // forward_score = off*ln2 + log( (expM @ e)[STOP] ); pending renorm in off.
    // Final dot in FULL f32 precision (one step, use plain shfl broadcast).
    {
        float a0 = 0.f, a1 = 0.f;
#pragma unroll
        for (int p = 0; p < 30; p += 2) {
            a0 = fmaf(M[p    ], __shfl_sync(FULLMASK, e, p    ), a0);
            a1 = fmaf(M[p + 1], __shfl_sync(FULLMASK, e, p + 1), a1);
        }
        float sfin  = a0 + a1;
        float sstop = __shfl_sync(FULLMASK, sfin, STOP_IDX);
        if (lane == 0)
            g_fwd[b] = (float)off * LN2 + __logf(sstop);
    }

    // ---- fused mean: last block reduces (fwd - gold) deterministically ----
    __shared__ unsigned sh_last;
    __syncthreads();
    if (lane == 0) {
        __threadfence();
        unsigned old = atomicAdd(&g_count, 1u);
        sh_last = (old == gridDim.x - 1) ? 1u : 0u;
    }
    __syncthreads();
    if (sh_last) {
        __threadfence();
        float v = 0.0f;
        for (int i = lane; i < B; i += 32)       // fixed order -> deterministic
            v += g_fwd[i] - g_gold[i];
#pragma unroll
        for (int d = 16; d; d >>= 1)
            v += __shfl_xor_sync(FULLMASK, v, d);
        if (lane == 0) {
            out[0] = v / (float)B;
            g_count = 0;                         // reset for next graph replay
        }
    }
}

// Gold score: embarrassingly parallel. One warp per batch, lanes stride t.
__global__ void __launch_bounds__(128)
crf_gold_kernel(const float* __restrict__ feats,
                const float* __restrict__ trans,
                const int*   __restrict__ tags,
                const int*   __restrict__ lens,
                int B, int T)
{
    __shared__ float sh_trans[KSTATES * KSTATES];
    const int tid  = threadIdx.x;
    const int wid  = tid >> 5;
    const int lane = tid & 31;

    for (int i = tid; i < KSTATES * KSTATES; i += 128)
        sh_trans[i] = trans[i];
    __syncthreads();

    const int b = blockIdx.x * 4 + wid;
    if (b >= B) return;

    const int* tb = tags + (size_t)b * T;
    const float* fbase = feats + (size_t)b * T * KSTATES;
    const int len = lens[b];

    float g = 0.0f;
    for (int t = lane; t < len; t += 32) {
        int tg    = tb[t];
        int tprev = (t == 0) ? START_IDX : tb[t - 1];
        g += fbase[(size_t)t * KSTATES + tg] + sh_trans[tg * KSTATES + tprev];
    }
#pragma unroll
    for (int d = 16; d; d >>= 1)
        g += __shfl_xor_sync(FULLMASK, g, d);
    if (lane == 0)
        g_gold[b] = g + sh_trans[STOP_IDX * KSTATES + tb[len - 1]];
}

extern "C" void kernel_launch(void* const* d_in, const int* in_sizes, int n_in,
                              void* d_out, int out_size)
{
    const float* feats = (const float*)d_in[0];   // [B,T,K] f32
    const float* trans = (const float*)d_in[1];   // [K,K]   f32
    const int*   tags  = (const int*)  d_in[2];   // [B,T]   i32
    const int*   lens  = (const int*)  d_in[3];   // [B]     i32

    int B = in_sizes[3];
    int T = in_sizes[2] / B;

    crf_gold_kernel<<<(B + 3) / 4, 128>>>(feats, trans, tags, lens, B, T);
    crf_forward_kernel<<<B, 32>>>(feats, trans, lens, (float*)d_out, B, T);
}